// round 7
// baseline (speedup 1.0000x reference)
#include <cuda_runtime.h>

#define BATCH 2
#define SEQ   2048
#define DMODEL 2048
#define NH    32
#define NG    8
#define DKH   64
#define GDK   (NG * DKH)    // 512
#define MROWS (BATCH * SEQ) // 4096

// ---------------- scratch (no cudaMalloc allowed) ----------------
__device__ unsigned g_xt [MROWS * DMODEL];
__device__ unsigned g_Qt [MROWS * DMODEL];
__device__ unsigned g_Kt [MROWS * GDK];
__device__ unsigned g_Vt [MROWS * GDK];
__device__ unsigned g_Ct [MROWS * DMODEL];
__device__ unsigned g_Wqt[DMODEL * DMODEL];
__device__ unsigned g_Wkt[DMODEL * GDK];
__device__ unsigned g_Wvt[DMODEL * GDK];
__device__ unsigned g_Wot[DMODEL * DMODEL];

// ---------------- helpers ----------------
__device__ __forceinline__ unsigned f2tf32(float x) {
    unsigned r; asm("cvt.rna.tf32.f32 %0, %1;" : "=r"(r) : "f"(x)); return r;
}
__device__ __forceinline__ void mma_tf32(float* d, const unsigned* a, const unsigned* b) {
    asm volatile(
        "mma.sync.aligned.m16n8k8.row.col.f32.tf32.tf32.f32 "
        "{%0,%1,%2,%3}, {%4,%5,%6,%7}, {%8,%9}, {%0,%1,%2,%3};"
        : "+f"(d[0]), "+f"(d[1]), "+f"(d[2]), "+f"(d[3])
        : "r"(a[0]), "r"(a[1]), "r"(a[2]), "r"(a[3]), "r"(b[0]), "r"(b[1]));
}
__device__ __forceinline__ unsigned smem_u32(const void* p) {
    unsigned a;
    asm("{ .reg .u64 t; cvta.to.shared.u64 t, %1; cvt.u32.u64 %0, t; }" : "=r"(a) : "l"(p));
    return a;
}
__device__ __forceinline__ void cp16(unsigned saddr, const void* g) {
    asm volatile("cp.async.cg.shared.global [%0], [%1], 16;" :: "r"(saddr), "l"(g));
}
#define CP_COMMIT() asm volatile("cp.async.commit_group;" ::: "memory")
#define CP_WAIT(n)  asm volatile("cp.async.wait_group %0;" :: "n"(n) : "memory")

// ---------------- fp32 -> tf32-word conversion ----------------
__global__ __launch_bounds__(256) void cvt_tf32_kernel(
    const float* __restrict__ in, unsigned* __restrict__ out, int n4)
{
    int i = blockIdx.x * blockDim.x + threadIdx.x;
    if (i >= n4) return;
    float4 v = ((const float4*)in)[i];
    ((uint4*)out)[i] = make_uint4(f2tf32(v.x), f2tf32(v.y), f2tf32(v.z), f2tf32(v.w));
}

// ---------------- tf32 GEMM, 3-stage cp.async ring ----------------
#define AST 36
#define BST 136
#define A_WORDS (128 * AST)          // 4608
#define B_WORDS (32 * BST)           // 4352
#define STG_WORDS (A_WORDS + B_WORDS)
#define GEMM_SMEM (3 * STG_WORDS * 4)   // 107520 B

template <bool OUT_TF32>
__global__ __launch_bounds__(256) void gemm_tf32_cp_kernel(
    const unsigned* __restrict__ A, const unsigned* __restrict__ B,
    const float* __restrict__ bias, void* __restrict__ Cout, int N, int K)
{
    extern __shared__ unsigned sm[];
    const unsigned sbase = smem_u32(sm);
    const int tid  = threadIdx.x;
    const int warp = tid >> 5;
    const int lane = tid & 31;
    const int grp  = lane >> 2;
    const int tig  = lane & 3;
    const int bm = blockIdx.y * 128;
    const int bn = blockIdx.x * 128;
    const int wm = (warp >> 2) * 64;
    const int wn = (warp & 3) * 32;

    float acc[4][4][4];
#pragma unroll
    for (int mt = 0; mt < 4; mt++)
#pragma unroll
        for (int nt = 0; nt < 4; nt++)
#pragma unroll
            for (int f = 0; f < 4; f++) acc[mt][nt][f] = 0.0f;

    const int NC = K >> 5;

    auto load_chunk = [&](int kc, int st) {
        unsigned abase = sbase + (st * STG_WORDS) * 4;
        unsigned bbase = abase + A_WORDS * 4;
        const unsigned* gA = A + (size_t)bm * K + kc * 32;
        const unsigned* gB = B + (size_t)(kc * 32) * N + bn;
#pragma unroll
        for (int it = 0; it < 4; it++) {
            int i = tid + it * 256;
            int m  = i >> 3, k4 = i & 7;
            cp16(abase + (m * AST + k4 * 4) * 4, gA + (size_t)m * K + k4 * 4);
            int k  = i >> 5, n4 = i & 31;
            cp16(bbase + (k * BST + n4 * 4) * 4, gB + (size_t)k * N + n4 * 4);
        }
        CP_COMMIT();
    };

    load_chunk(0, 0);
    if (NC > 1) load_chunk(1, 1);
    for (int c = 0; c < NC; c++) {
        const int st = c % 3;
        if (c + 2 < NC) { load_chunk(c + 2, (c + 2) % 3); CP_WAIT(2); }
        else if (c + 1 < NC) { CP_WAIT(1); }
        else { CP_WAIT(0); }
        __syncthreads();

        const unsigned* smA = sm + st * STG_WORDS;
        const unsigned* smB = smA + A_WORDS;
#pragma unroll
        for (int ks = 0; ks < 32; ks += 8) {
            unsigned af[4][4], bf[4][2];
#pragma unroll
            for (int mt = 0; mt < 4; mt++) {
                int r0 = wm + mt * 16 + grp;
                af[mt][0] = smA[r0 * AST + ks + tig];
                af[mt][1] = smA[(r0 + 8) * AST + ks + tig];
                af[mt][2] = smA[r0 * AST + ks + tig + 4];
                af[mt][3] = smA[(r0 + 8) * AST + ks + tig + 4];
            }
#pragma unroll
            for (int nt = 0; nt < 4; nt++) {
                int c0 = wn + nt * 8 + grp;
                bf[nt][0] = smB[(ks + tig) * BST + c0];
                bf[nt][1] = smB[(ks + tig + 4) * BST + c0];
            }
#pragma unroll
            for (int mt = 0; mt < 4; mt++)
#pragma unroll
                for (int nt = 0; nt < 4; nt++)
                    mma_tf32(acc[mt][nt], af[mt], bf[nt]);
        }
        __syncthreads();
    }

#pragma unroll
    for (int mt = 0; mt < 4; mt++) {
        int r0 = bm + wm + mt * 16 + grp;
#pragma unroll
        for (int nt = 0; nt < 4; nt++) {
            int c0 = bn + wn + nt * 8 + 2 * tig;
            float b0 = bias[c0], b1 = bias[c0 + 1];
            float v00 = acc[mt][nt][0] + b0, v01 = acc[mt][nt][1] + b1;
            float v10 = acc[mt][nt][2] + b0, v11 = acc[mt][nt][3] + b1;
            if (OUT_TF32) {
                unsigned* C = (unsigned*)Cout;
                *(uint2*)(C + (size_t)r0 * N + c0) = make_uint2(f2tf32(v00), f2tf32(v01));
                *(uint2*)(C + (size_t)(r0 + 8) * N + c0) = make_uint2(f2tf32(v10), f2tf32(v11));
            } else {
                float* C = (float*)Cout;
                *(float2*)(C + (size_t)r0 * N + c0) = make_float2(v00, v01);
                *(float2*)(C + (size_t)(r0 + 8) * N + c0) = make_float2(v10, v11);
            }
        }
    }
}

// ---------------- flash attention: 128 queries/block, 32 rows/warp ----------------
#define QST 68
#define VST 72
#define SM_QOFF 0
#define SM_KPOFF (128 * QST)                 // K tile rows 0..63, then P rows 0..127
#define SM_VOFF (SM_KPOFF + 128 * QST)
#define ATTN_SMEM_WORDS (SM_VOFF + 64 * VST) // 22016 words = 88064 B

__global__ __launch_bounds__(128) void gqa_attn_tf32_kernel(
    const unsigned* __restrict__ Q, const unsigned* __restrict__ Kb,
    const unsigned* __restrict__ Vb, unsigned* __restrict__ O)
{
    extern __shared__ unsigned sm[];
    unsigned* Qs  = sm + SM_QOFF;
    unsigned* KPs = sm + SM_KPOFF;
    unsigned* Vs  = sm + SM_VOFF;

    const int h  = blockIdx.y;
    const int b  = blockIdx.z;
    const int g  = h >> 2;
    const int q0 = blockIdx.x * 128;
    const int tid  = threadIdx.x;
    const int warp = tid >> 5;
    const int lane = tid & 31;
    const int grp  = lane >> 2;
    const int tig  = lane & 3;
    const int wq0 = warp * 32;          // warp's query-row base (within 128)

    // load Q tile: 128 rows x 64 cols (tf32 words)
    for (int e = tid; e < 2048; e += 128) {
        int q = e >> 4, d4 = e & 15;
        *(uint4*)&Qs[q * QST + d4 * 4] =
            *(const uint4*)(Q + (size_t)(b * SEQ + q0 + q) * DMODEL + h * DKH + d4 * 4);
    }

    float oacc[2][8][4];
#pragma unroll
    for (int mt = 0; mt < 2; mt++)
#pragma unroll
        for (int nt = 0; nt < 8; nt++)
#pragma unroll
            for (int f = 0; f < 4; f++) oacc[mt][nt][f] = 0.0f;
    float m_run[4], l_run[4];
#pragma unroll
    for (int s = 0; s < 4; s++) { m_run[s] = -1e30f; l_run[s] = 0.0f; }
    const float scale = 0.125f;

    for (int kt = 0; kt < SEQ; kt += 64) {
        // stage K (rows 0..63 of KPs) and V
        for (int e = tid; e < 1024; e += 128) {
            int j = e >> 4, d4 = e & 15;
            size_t gidx = (size_t)(b * SEQ + kt + j) * GDK + g * DKH + d4 * 4;
            *(uint4*)&KPs[j * QST + d4 * 4] = *(const uint4*)(Kb + gidx);
            *(uint4*)&Vs[j * VST + d4 * 4]  = *(const uint4*)(Vb + gidx);
        }
        __syncthreads();

        // S = Q K^T : warp computes 32 rows x 64 keys
        float sacc[2][8][4];
#pragma unroll
        for (int mt = 0; mt < 2; mt++)
#pragma unroll
            for (int nt = 0; nt < 8; nt++)
#pragma unroll
                for (int f = 0; f < 4; f++) sacc[mt][nt][f] = 0.0f;

#pragma unroll
        for (int ks = 0; ks < 8; ks++) {
            int d = ks * 8;
            unsigned af[2][4];
#pragma unroll
            for (int mt = 0; mt < 2; mt++) {
                int r0 = wq0 + mt * 16 + grp;
                af[mt][0] = Qs[r0 * QST + d + tig];
                af[mt][1] = Qs[(r0 + 8) * QST + d + tig];
                af[mt][2] = Qs[r0 * QST + d + tig + 4];
                af[mt][3] = Qs[(r0 + 8) * QST + d + tig + 4];
            }
#pragma unroll
            for (int nt = 0; nt < 8; nt++) {
                unsigned bf[2];
                bf[0] = KPs[(nt * 8 + grp) * QST + d + tig];
                bf[1] = KPs[(nt * 8 + grp) * QST + d + tig + 4];
#pragma unroll
                for (int mt = 0; mt < 2; mt++)
                    mma_tf32(sacc[mt][nt], af[mt], bf);
            }
        }
        __syncthreads();   // all warps done reading K; KPs becomes P

        // online softmax: 4 row-streams (mt*2 + half)
        float rmax[4] = {-1e30f, -1e30f, -1e30f, -1e30f};
#pragma unroll
        for (int mt = 0; mt < 2; mt++)
#pragma unroll
            for (int nt = 0; nt < 8; nt++) {
#pragma unroll
                for (int f = 0; f < 4; f++) sacc[mt][nt][f] *= scale;
                rmax[mt * 2]     = fmaxf(rmax[mt * 2],     fmaxf(sacc[mt][nt][0], sacc[mt][nt][1]));
                rmax[mt * 2 + 1] = fmaxf(rmax[mt * 2 + 1], fmaxf(sacc[mt][nt][2], sacc[mt][nt][3]));
            }
#pragma unroll
        for (int s = 0; s < 4; s++) {
#pragma unroll
            for (int o = 1; o <= 2; o <<= 1)
                rmax[s] = fmaxf(rmax[s], __shfl_xor_sync(0xffffffffu, rmax[s], o));
        }
        float mn[4], ls[4] = {0.f, 0.f, 0.f, 0.f};
#pragma unroll
        for (int s = 0; s < 4; s++) mn[s] = fmaxf(m_run[s], rmax[s]);

#pragma unroll
        for (int mt = 0; mt < 2; mt++) {
            int r0 = wq0 + mt * 16 + grp;
#pragma unroll
            for (int nt = 0; nt < 8; nt++) {
                float p0 = __expf(sacc[mt][nt][0] - mn[mt * 2]);
                float p1 = __expf(sacc[mt][nt][1] - mn[mt * 2]);
                float p2 = __expf(sacc[mt][nt][2] - mn[mt * 2 + 1]);
                float p3 = __expf(sacc[mt][nt][3] - mn[mt * 2 + 1]);
                ls[mt * 2]     += p0 + p1;
                ls[mt * 2 + 1] += p2 + p3;
                int c = nt * 8 + 2 * tig;
                KPs[r0 * QST + c]           = f2tf32(p0);
                KPs[r0 * QST + c + 1]       = f2tf32(p1);
                KPs[(r0 + 8) * QST + c]     = f2tf32(p2);
                KPs[(r0 + 8) * QST + c + 1] = f2tf32(p3);
            }
        }
#pragma unroll
        for (int s = 0; s < 4; s++) {
#pragma unroll
            for (int o = 1; o <= 2; o <<= 1)
                ls[s] += __shfl_xor_sync(0xffffffffu, ls[s], o);
            float al = __expf(m_run[s] - mn[s]);
            l_run[s] = l_run[s] * al + ls[s];
            m_run[s] = mn[s];
            int mt = s >> 1, half = s & 1;
#pragma unroll
            for (int nt = 0; nt < 8; nt++) {
                oacc[mt][nt][half * 2]     *= al;
                oacc[mt][nt][half * 2 + 1] *= al;
            }
        }
        __syncwarp();   // P rows are warp-private

        // O += P V : 32 rows x 64 dv
#pragma unroll
        for (int ks = 0; ks < 8; ks++) {
            int j = ks * 8;
            unsigned af[2][4];
#pragma unroll
            for (int mt = 0; mt < 2; mt++) {
                int r0 = wq0 + mt * 16 + grp;
                af[mt][0] = KPs[r0 * QST + j + tig];
                af[mt][1] = KPs[(r0 + 8) * QST + j + tig];
                af[mt][2] = KPs[r0 * QST + j + tig + 4];
                af[mt][3] = KPs[(r0 + 8) * QST + j + tig + 4];
            }
#pragma unroll
            for (int nt = 0; nt < 8; nt++) {
                unsigned bf[2];
                bf[0] = Vs[(j + tig) * VST + nt * 8 + grp];
                bf[1] = Vs[(j + tig + 4) * VST + nt * 8 + grp];
#pragma unroll
                for (int mt = 0; mt < 2; mt++)
                    mma_tf32(oacc[mt][nt], af[mt], bf);
            }
        }
        __syncthreads();   // before next tile overwrites KPs/Vs
    }

    // epilogue: write context as tf32 words
#pragma unroll
    for (int mt = 0; mt < 2; mt++) {
        float inv0 = 1.0f / l_run[mt * 2];
        float inv1 = 1.0f / l_run[mt * 2 + 1];
        size_t rowA = (size_t)(b * SEQ + q0 + wq0 + mt * 16 + grp) * DMODEL + h * DKH;
        size_t rowB = rowA + (size_t)8 * DMODEL;
#pragma unroll
        for (int nt = 0; nt < 8; nt++) {
            int c = nt * 8 + 2 * tig;
            *(uint2*)(O + rowA + c) =
                make_uint2(f2tf32(oacc[mt][nt][0] * inv0), f2tf32(oacc[mt][nt][1] * inv0));
            *(uint2*)(O + rowB + c) =
                make_uint2(f2tf32(oacc[mt][nt][2] * inv1), f2tf32(oacc[mt][nt][3] * inv1));
        }
    }
}

// ---------------- host ----------------
extern "C" void kernel_launch(void* const* d_in, const int* in_sizes, int n_in,
                              void* d_out, int out_size)
{
    const float* x  = (const float*)d_in[0];
    const float* Wq = (const float*)d_in[1];
    const float* bq = (const float*)d_in[2];
    const float* Wk = (const float*)d_in[3];
    const float* bk = (const float*)d_in[4];
    const float* Wv = (const float*)d_in[5];
    const float* bv = (const float*)d_in[6];
    const float* Wo = (const float*)d_in[7];
    const float* bo = (const float*)d_in[8];
    float* out = (float*)d_out;

    unsigned *xt, *Qt, *Kt, *Vt, *Ct, *Wqt, *Wkt, *Wvt, *Wot;
    cudaGetSymbolAddress((void**)&xt,  g_xt);
    cudaGetSymbolAddress((void**)&Qt,  g_Qt);
    cudaGetSymbolAddress((void**)&Kt,  g_Kt);
    cudaGetSymbolAddress((void**)&Vt,  g_Vt);
    cudaGetSymbolAddress((void**)&Ct,  g_Ct);
    cudaGetSymbolAddress((void**)&Wqt, g_Wqt);
    cudaGetSymbolAddress((void**)&Wkt, g_Wkt);
    cudaGetSymbolAddress((void**)&Wvt, g_Wvt);
    cudaGetSymbolAddress((void**)&Wot, g_Wot);

    const int attn_smem = ATTN_SMEM_WORDS * (int)sizeof(unsigned);
    cudaFuncSetAttribute(gqa_attn_tf32_kernel,
                         cudaFuncAttributeMaxDynamicSharedMemorySize, attn_smem);
    cudaFuncSetAttribute(gemm_tf32_cp_kernel<true>,
                         cudaFuncAttributeMaxDynamicSharedMemorySize, GEMM_SMEM);
    cudaFuncSetAttribute(gemm_tf32_cp_kernel<false>,
                         cudaFuncAttributeMaxDynamicSharedMemorySize, GEMM_SMEM);

    cvt_tf32_kernel<<<(MROWS * DMODEL / 4 + 255) / 256, 256>>>(x,  xt,  MROWS * DMODEL / 4);
    cvt_tf32_kernel<<<(DMODEL * DMODEL / 4 + 255) / 256, 256>>>(Wq, Wqt, DMODEL * DMODEL / 4);
    cvt_tf32_kernel<<<(DMODEL * GDK / 4 + 255) / 256, 256>>>(Wk, Wkt, DMODEL * GDK / 4);
    cvt_tf32_kernel<<<(DMODEL * GDK / 4 + 255) / 256, 256>>>(Wv, Wvt, DMODEL * GDK / 4);
    cvt_tf32_kernel<<<(DMODEL * DMODEL / 4 + 255) / 256, 256>>>(Wo, Wot, DMODEL * DMODEL / 4);

    gemm_tf32_cp_kernel<true><<<dim3(DMODEL / 128, MROWS / 128), 256, GEMM_SMEM>>>(
        xt, Wqt, bq, Qt, DMODEL, DMODEL);
    gemm_tf32_cp_kernel<true><<<dim3(GDK / 128, MROWS / 128), 256, GEMM_SMEM>>>(
        xt, Wkt, bk, Kt, GDK, DMODEL);
    gemm_tf32_cp_kernel<true><<<dim3(GDK / 128, MROWS / 128), 256, GEMM_SMEM>>>(
        xt, Wvt, bv, Vt, GDK, DMODEL);

    gqa_attn_tf32_kernel<<<dim3(SEQ / 128, NH, BATCH), 128, attn_smem>>>(Qt, Kt, Vt, Ct);

    gemm_tf32_cp_kernel<false><<<dim3(DMODEL / 128, MROWS / 128), 256, GEMM_SMEM>>>(
        Ct, Wot, bo, out, DMODEL, DMODEL);
}

// round 8
// speedup vs baseline: 1.9333x; 1.9333x over previous
#include <cuda_runtime.h>
#include <cuda_fp16.h>

#define BATCH 2
#define SEQ   2048
#define DMODEL 2048
#define NH    32
#define NG    8
#define DKH   64
#define GDK   (NG * DKH)    // 512
#define MROWS (BATCH * SEQ) // 4096

// ---------------- scratch (no cudaMalloc allowed) ----------------
__device__ __half g_xh [MROWS * DMODEL];
__device__ __half g_Qh [MROWS * DMODEL];
__device__ __half g_Kh [MROWS * GDK];
__device__ __half g_Vh [MROWS * GDK];
__device__ __half g_Ch [MROWS * DMODEL];
__device__ __half g_Wqt[DMODEL * DMODEL];   // [n][k]
__device__ __half g_Wkt[GDK * DMODEL];
__device__ __half g_Wvt[GDK * DMODEL];
__device__ __half g_Wot[DMODEL * DMODEL];

// ---------------- helpers ----------------
__device__ __forceinline__ unsigned smem_u32(const void* p) {
    unsigned a;
    asm("{ .reg .u64 t; cvta.to.shared.u64 t, %1; cvt.u32.u64 %0, t; }" : "=r"(a) : "l"(p));
    return a;
}
__device__ __forceinline__ void cp16(unsigned saddr, const void* g) {
    asm volatile("cp.async.cg.shared.global [%0], [%1], 16;" :: "r"(saddr), "l"(g));
}
#define CP_COMMIT() asm volatile("cp.async.commit_group;" ::: "memory")
#define CP_WAIT(n)  asm volatile("cp.async.wait_group %0;" :: "n"(n) : "memory")

__device__ __forceinline__ void ldm_x4(unsigned* r, unsigned saddr) {
    asm volatile("ldmatrix.sync.aligned.m8n8.x4.shared.b16 {%0,%1,%2,%3}, [%4];"
        : "=r"(r[0]), "=r"(r[1]), "=r"(r[2]), "=r"(r[3]) : "r"(saddr));
}
__device__ __forceinline__ void ldm_x4_t(unsigned* r, unsigned saddr) {
    asm volatile("ldmatrix.sync.aligned.m8n8.x4.trans.shared.b16 {%0,%1,%2,%3}, [%4];"
        : "=r"(r[0]), "=r"(r[1]), "=r"(r[2]), "=r"(r[3]) : "r"(saddr));
}
__device__ __forceinline__ void mma_f16(float* d, const unsigned* a, unsigned b0, unsigned b1) {
    asm volatile(
        "mma.sync.aligned.m16n8k16.row.col.f32.f16.f16.f32 "
        "{%0,%1,%2,%3}, {%4,%5,%6,%7}, {%8,%9}, {%0,%1,%2,%3};"
        : "+f"(d[0]), "+f"(d[1]), "+f"(d[2]), "+f"(d[3])
        : "r"(a[0]), "r"(a[1]), "r"(a[2]), "r"(a[3]), "r"(b0), "r"(b1));
}
__device__ __forceinline__ unsigned h2u(float a, float b) {
    __half2 h = __floats2half2_rn(a, b);
    return *reinterpret_cast<unsigned*>(&h);
}

// ---------------- prep kernels ----------------
__global__ __launch_bounds__(256) void cvt_half_kernel(
    const float* __restrict__ in, __half* __restrict__ out, int n4)
{
    int i = blockIdx.x * blockDim.x + threadIdx.x;
    if (i >= n4) return;
    float4 v = ((const float4*)in)[i];
    __half2 h0 = __floats2half2_rn(v.x, v.y);
    __half2 h1 = __floats2half2_rn(v.z, v.w);
    ((__half2*)out)[2 * i]     = h0;
    ((__half2*)out)[2 * i + 1] = h1;
}

// W [K][N] fp32 -> T [N][K] fp16
__global__ __launch_bounds__(256) void transpose_half_kernel(
    const float* __restrict__ W, __half* __restrict__ T, int K, int N)
{
    __shared__ float t[32][33];
    int n0 = blockIdx.x * 32, k0 = blockIdx.y * 32;
    int tx = threadIdx.x & 31, ty = threadIdx.x >> 5;
#pragma unroll
    for (int s = 0; s < 4; s++)
        t[ty + 8 * s][tx] = W[(size_t)(k0 + ty + 8 * s) * N + n0 + tx];
    __syncthreads();
#pragma unroll
    for (int s = 0; s < 4; s++)
        T[(size_t)(n0 + ty + 8 * s) * K + k0 + tx] = __float2half(t[tx][ty + 8 * s]);
}

// ---------------- fp16 GEMM, ldmatrix + cp.async 3-stage ----------------
// C[M,N] = A[M,K] * Bt[N,K]^T + bias.  BK=32 halves.
#define HST 40                       // smem row stride in halves (80 B)
#define TILE_H (128 * HST)           // 5120 halves per operand tile
#define STG_H (2 * TILE_H)           // A + B per stage
#define GEMM_SMEM (3 * STG_H * 2)    // 61440 B

template <bool OUT_HALF>
__global__ __launch_bounds__(256) void gemm_f16_kernel(
    const __half* __restrict__ A, const __half* __restrict__ Bt,
    const float* __restrict__ bias, void* __restrict__ Cout, int N, int K)
{
    extern __shared__ __half smh[];
    const unsigned sbase = smem_u32(smh);
    const int tid  = threadIdx.x;
    const int warp = tid >> 5;
    const int lane = tid & 31;
    const int grp  = lane >> 2;
    const int tig  = lane & 3;
    const int bm = blockIdx.y * 128;
    const int bn = blockIdx.x * 128;
    const int wm = (warp >> 2) * 64;
    const int wn = (warp & 3) * 32;

    // ldmatrix lane address components
    const int lrow = (lane & 7) + 8 * ((lane >> 3) & 1);  // A-style: mats row-major pairs
    const int lseg = lane >> 4;
    const int brow = (lane & 7) + 8 * (lane >> 4);        // B-style
    const int bseg = (lane >> 3) & 1;

    float acc[4][4][4];
#pragma unroll
    for (int mt = 0; mt < 4; mt++)
#pragma unroll
        for (int nt = 0; nt < 4; nt++)
#pragma unroll
            for (int f = 0; f < 4; f++) acc[mt][nt][f] = 0.0f;

    const int NC = K >> 5;

    auto load_chunk = [&](int kc, int st) {
        unsigned ab = sbase + st * (STG_H * 2);
        unsigned bb = ab + TILE_H * 2;
        const __half* gA = A  + (size_t)bm * K + kc * 32;
        const __half* gB = Bt + (size_t)bn * K + kc * 32;
#pragma unroll
        for (int it = 0; it < 2; it++) {
            int i = tid + it * 256;        // 0..511
            int r = i >> 2, ch = i & 3;
            cp16(ab + r * 80 + ch * 16, gA + (size_t)r * K + ch * 8);
        }
#pragma unroll
        for (int it = 0; it < 2; it++) {
            int i = tid + it * 256;
            int r = i >> 2, ch = i & 3;
            cp16(bb + r * 80 + ch * 16, gB + (size_t)r * K + ch * 8);
        }
        CP_COMMIT();
    };

    load_chunk(0, 0);
    if (NC > 1) load_chunk(1, 1);
    for (int c = 0; c < NC; c++) {
        const int st = c % 3;
        if (c + 2 < NC)      { load_chunk(c + 2, (c + 2) % 3); CP_WAIT(2); }
        else if (c + 1 < NC) { CP_WAIT(1); }
        else                 { CP_WAIT(0); }
        __syncthreads();

        const unsigned sA = sbase + st * (STG_H * 2);
        const unsigned sB = sA + TILE_H * 2;
#pragma unroll
        for (int kb = 0; kb < 32; kb += 16) {
            unsigned a[4][4], bq[2][4];
#pragma unroll
            for (int mt = 0; mt < 4; mt++)
                ldm_x4(a[mt], sA + ((wm + mt * 16 + lrow) * HST + kb + 8 * lseg) * 2);
#pragma unroll
            for (int np = 0; np < 2; np++)
                ldm_x4(bq[np], sB + ((wn + np * 16 + brow) * HST + kb + 8 * bseg) * 2);
#pragma unroll
            for (int mt = 0; mt < 4; mt++)
#pragma unroll
                for (int np = 0; np < 2; np++) {
                    mma_f16(acc[mt][2 * np],     a[mt], bq[np][0], bq[np][1]);
                    mma_f16(acc[mt][2 * np + 1], a[mt], bq[np][2], bq[np][3]);
                }
        }
        __syncthreads();
    }

    // epilogue
#pragma unroll
    for (int mt = 0; mt < 4; mt++) {
        int r0 = bm + wm + mt * 16 + grp;
#pragma unroll
        for (int nt = 0; nt < 4; nt++) {
            int c0 = bn + wn + nt * 8 + 2 * tig;
            float b0 = bias[c0], b1 = bias[c0 + 1];
            float v00 = acc[mt][nt][0] + b0, v01 = acc[mt][nt][1] + b1;
            float v10 = acc[mt][nt][2] + b0, v11 = acc[mt][nt][3] + b1;
            if (OUT_HALF) {
                __half* C = (__half*)Cout;
                *(unsigned*)(C + (size_t)r0 * N + c0)       = h2u(v00, v01);
                *(unsigned*)(C + (size_t)(r0 + 8) * N + c0) = h2u(v10, v11);
            } else {
                float* C = (float*)Cout;
                *(float2*)(C + (size_t)r0 * N + c0)       = make_float2(v00, v01);
                *(float2*)(C + (size_t)(r0 + 8) * N + c0) = make_float2(v10, v11);
            }
        }
    }
}

// ---------------- flash attention, fp16 mma, P in registers ----------------
// 64 queries/block, 128 threads (4 warps), 16 query rows per warp.
// smem halves: Qs 64x72, Ks 64x72, Vs 64x72  -> 27648 B
#define AQST 72
#define ATTN_SMEM (3 * 64 * AQST * 2)

__global__ __launch_bounds__(128) void gqa_attn_f16_kernel(
    const __half* __restrict__ Q, const __half* __restrict__ Kb,
    const __half* __restrict__ Vb, __half* __restrict__ O)
{
    extern __shared__ __half sh[];
    const unsigned sb = smem_u32(sh);
    const unsigned Qb  = sb;
    const unsigned Kbs = sb + 64 * AQST * 2;
    const unsigned Vbs = sb + 2 * 64 * AQST * 2;

    const int h  = blockIdx.y;
    const int b  = blockIdx.z;
    const int g  = h >> 2;
    const int q0 = blockIdx.x * 64;
    const int tid  = threadIdx.x;
    const int warp = tid >> 5;
    const int lane = tid & 31;
    const int grp  = lane >> 2;
    const int tig  = lane & 3;
    const int wq0 = warp * 16;

    const int lrow = (lane & 7) + 8 * ((lane >> 3) & 1);
    const int lseg = lane >> 4;
    const int brow = (lane & 7) + 8 * (lane >> 4);
    const int bseg = (lane >> 3) & 1;

    // load Q tile: 64 rows x 64 halves
    for (int e = tid; e < 512; e += 128) {
        int r = e >> 3, s = e & 7;
        *(uint4*)(sh + r * AQST + s * 8) =
            *(const uint4*)(Q + (size_t)(b * SEQ + q0 + r) * DMODEL + h * DKH + s * 8);
    }

    float oacc[8][4];
#pragma unroll
    for (int nt = 0; nt < 8; nt++)
#pragma unroll
        for (int f = 0; f < 4; f++) oacc[nt][f] = 0.0f;
    float mA = -1e30f, mB = -1e30f, lA = 0.0f, lB = 0.0f;
    const float scale = 0.125f;

    for (int kt = 0; kt < SEQ; kt += 64) {
        for (int e = tid; e < 512; e += 128) {
            int r = e >> 3, s = e & 7;
            size_t gi = (size_t)(b * SEQ + kt + r) * GDK + g * DKH + s * 8;
            *(uint4*)(sh + 64 * AQST + r * AQST + s * 8) = *(const uint4*)(Kb + gi);
            *(uint4*)(sh + 128 * AQST + r * AQST + s * 8) = *(const uint4*)(Vb + gi);
        }
        __syncthreads();

        // S = Q K^T : 16 rows x 64 keys, 4 k16-steps
        float sacc[8][4];
#pragma unroll
        for (int nt = 0; nt < 8; nt++)
#pragma unroll
            for (int f = 0; f < 4; f++) sacc[nt][f] = 0.0f;

#pragma unroll
        for (int ks = 0; ks < 4; ks++) {
            int kb = ks * 16;
            unsigned a[4];
            ldm_x4(a, Qb + ((wq0 + lrow) * AQST + kb + 8 * lseg) * 2);
#pragma unroll
            for (int np = 0; np < 4; np++) {
                unsigned bq[4];
                ldm_x4(bq, Kbs + ((np * 16 + brow) * AQST + kb + 8 * bseg) * 2);
                mma_f16(sacc[2 * np],     a, bq[0], bq[1]);
                mma_f16(sacc[2 * np + 1], a, bq[2], bq[3]);
            }
        }

        // online softmax (rows grp -> stream A, grp+8 -> stream B)
        float rmaxA = -1e30f, rmaxB = -1e30f;
#pragma unroll
        for (int nt = 0; nt < 8; nt++) {
#pragma unroll
            for (int f = 0; f < 4; f++) sacc[nt][f] *= scale;
            rmaxA = fmaxf(rmaxA, fmaxf(sacc[nt][0], sacc[nt][1]));
            rmaxB = fmaxf(rmaxB, fmaxf(sacc[nt][2], sacc[nt][3]));
        }
#pragma unroll
        for (int o = 1; o <= 2; o <<= 1) {
            rmaxA = fmaxf(rmaxA, __shfl_xor_sync(0xffffffffu, rmaxA, o));
            rmaxB = fmaxf(rmaxB, __shfl_xor_sync(0xffffffffu, rmaxB, o));
        }
        float mnA = fmaxf(mA, rmaxA), mnB = fmaxf(mB, rmaxB);

        unsigned ph[8][2];
        float lsA = 0.0f, lsB = 0.0f;
#pragma unroll
        for (int nt = 0; nt < 8; nt++) {
            float p0 = __expf(sacc[nt][0] - mnA);
            float p1 = __expf(sacc[nt][1] - mnA);
            float p2 = __expf(sacc[nt][2] - mnB);
            float p3 = __expf(sacc[nt][3] - mnB);
            lsA += p0 + p1;  lsB += p2 + p3;
            ph[nt][0] = h2u(p0, p1);
            ph[nt][1] = h2u(p2, p3);
        }
#pragma unroll
        for (int o = 1; o <= 2; o <<= 1) {
            lsA += __shfl_xor_sync(0xffffffffu, lsA, o);
            lsB += __shfl_xor_sync(0xffffffffu, lsB, o);
        }
        float alA = __expf(mA - mnA), alB = __expf(mB - mnB);
        lA = lA * alA + lsA;  lB = lB * alB + lsB;
        mA = mnA;             mB = mnB;
#pragma unroll
        for (int nt = 0; nt < 8; nt++) {
            oacc[nt][0] *= alA; oacc[nt][1] *= alA;
            oacc[nt][2] *= alB; oacc[nt][3] *= alB;
        }

        // O += P V : P fragments come straight from registers
#pragma unroll
        for (int ks = 0; ks < 4; ks++) {
            int kb = ks * 16;
            unsigned a[4];
            a[0] = ph[2 * ks][0];
            a[1] = ph[2 * ks][1];
            a[2] = ph[2 * ks + 1][0];
            a[3] = ph[2 * ks + 1][1];
#pragma unroll
            for (int np = 0; np < 4; np++) {
                unsigned bv[4];
                ldm_x4_t(bv, Vbs + ((kb + lrow) * AQST + np * 16 + 8 * lseg) * 2);
                mma_f16(oacc[2 * np],     a, bv[0], bv[1]);
                mma_f16(oacc[2 * np + 1], a, bv[2], bv[3]);
            }
        }
        __syncthreads();   // before next tile overwrites K/V
    }

    // epilogue: write context fp16
    float invA = 1.0f / lA, invB = 1.0f / lB;
    size_t rowA = (size_t)(b * SEQ + q0 + wq0 + grp) * DMODEL + h * DKH;
    size_t rowB = rowA + (size_t)8 * DMODEL;
#pragma unroll
    for (int nt = 0; nt < 8; nt++) {
        int c = nt * 8 + 2 * tig;
        *(unsigned*)(O + rowA + c) = h2u(oacc[nt][0] * invA, oacc[nt][1] * invA);
        *(unsigned*)(O + rowB + c) = h2u(oacc[nt][2] * invB, oacc[nt][3] * invB);
    }
}

// ---------------- host ----------------
extern "C" void kernel_launch(void* const* d_in, const int* in_sizes, int n_in,
                              void* d_out, int out_size)
{
    const float* x  = (const float*)d_in[0];
    const float* Wq = (const float*)d_in[1];
    const float* bq = (const float*)d_in[2];
    const float* Wk = (const float*)d_in[3];
    const float* bk = (const float*)d_in[4];
    const float* Wv = (const float*)d_in[5];
    const float* bv = (const float*)d_in[6];
    const float* Wo = (const float*)d_in[7];
    const float* bo = (const float*)d_in[8];
    float* out = (float*)d_out;

    __half *xh, *Qh, *Kh, *Vh, *Ch, *Wqt, *Wkt, *Wvt, *Wot;
    cudaGetSymbolAddress((void**)&xh,  g_xh);
    cudaGetSymbolAddress((void**)&Qh,  g_Qh);
    cudaGetSymbolAddress((void**)&Kh,  g_Kh);
    cudaGetSymbolAddress((void**)&Vh,  g_Vh);
    cudaGetSymbolAddress((void**)&Ch,  g_Ch);
    cudaGetSymbolAddress((void**)&Wqt, g_Wqt);
    cudaGetSymbolAddress((void**)&Wkt, g_Wkt);
    cudaGetSymbolAddress((void**)&Wvt, g_Wvt);
    cudaGetSymbolAddress((void**)&Wot, g_Wot);

    cudaFuncSetAttribute(gqa_attn_f16_kernel,
                         cudaFuncAttributeMaxDynamicSharedMemorySize, ATTN_SMEM);
    cudaFuncSetAttribute(gemm_f16_kernel<true>,
                         cudaFuncAttributeMaxDynamicSharedMemorySize, GEMM_SMEM);
    cudaFuncSetAttribute(gemm_f16_kernel<false>,
                         cudaFuncAttributeMaxDynamicSharedMemorySize, GEMM_SMEM);

    // prep: x -> fp16, weights -> transposed fp16
    cvt_half_kernel<<<(MROWS * DMODEL / 4 + 255) / 256, 256>>>(x, xh, MROWS * DMODEL / 4);
    transpose_half_kernel<<<dim3(DMODEL / 32, DMODEL / 32), 256>>>(Wq, Wqt, DMODEL, DMODEL);
    transpose_half_kernel<<<dim3(GDK / 32, DMODEL / 32), 256>>>(Wk, Wkt, DMODEL, GDK);
    transpose_half_kernel<<<dim3(GDK / 32, DMODEL / 32), 256>>>(Wv, Wvt, DMODEL, GDK);
    transpose_half_kernel<<<dim3(DMODEL / 32, DMODEL / 32), 256>>>(Wo, Wot, DMODEL, DMODEL);

    // projections
    gemm_f16_kernel<true><<<dim3(DMODEL / 128, MROWS / 128), 256, GEMM_SMEM>>>(
        xh, Wqt, bq, Qh, DMODEL, DMODEL);
    gemm_f16_kernel<true><<<dim3(GDK / 128, MROWS / 128), 256, GEMM_SMEM>>>(
        xh, Wkt, bk, Kh, GDK, DMODEL);
    gemm_f16_kernel<true><<<dim3(GDK / 128, MROWS / 128), 256, GEMM_SMEM>>>(
        xh, Wvt, bv, Vh, GDK, DMODEL);

    // attention
    gqa_attn_f16_kernel<<<dim3(SEQ / 64, NH, BATCH), 128, ATTN_SMEM>>>(Qh, Kh, Vh, Ch);

    // output projection -> fp32
    gemm_f16_kernel<false><<<dim3(DMODEL / 128, MROWS / 128), 256, GEMM_SMEM>>>(
        Ch, Wot, bo, out, DMODEL, DMODEL);
}

// round 9
// speedup vs baseline: 2.0610x; 1.0661x over previous
#include <cuda_runtime.h>
#include <cuda_fp16.h>

#define BATCH 2
#define SEQ   2048
#define DMODEL 2048
#define NH    32
#define NG    8
#define DKH   64
#define GDK   (NG * DKH)    // 512
#define KVSTR (2 * GDK)     // 1024: fused K|V row stride
#define MROWS (BATCH * SEQ) // 4096

// ---------------- scratch (no cudaMalloc allowed) ----------------
__device__ __half g_xh  [MROWS * DMODEL];
__device__ __half g_Qh  [MROWS * DMODEL];
__device__ __half g_KVh [MROWS * KVSTR];    // cols 0..511 = K, 512..1023 = V
__device__ __half g_Ch  [MROWS * DMODEL];
__device__ __half g_Wqt [DMODEL * DMODEL];  // [n][k]
__device__ __half g_Wkvt[KVSTR * DMODEL];   // rows 0..511 Wk^T, 512..1023 Wv^T
__device__ __half g_Wot [DMODEL * DMODEL];
__device__ float  g_bkv [KVSTR];

// ---------------- helpers ----------------
__device__ __forceinline__ unsigned smem_u32(const void* p) {
    unsigned a;
    asm("{ .reg .u64 t; cvta.to.shared.u64 t, %1; cvt.u32.u64 %0, t; }" : "=r"(a) : "l"(p));
    return a;
}
__device__ __forceinline__ void cp16(unsigned saddr, const void* g) {
    asm volatile("cp.async.cg.shared.global [%0], [%1], 16;" :: "r"(saddr), "l"(g));
}
#define CP_COMMIT() asm volatile("cp.async.commit_group;" ::: "memory")
#define CP_WAIT(n)  asm volatile("cp.async.wait_group %0;" :: "n"(n) : "memory")

__device__ __forceinline__ void ldm_x4(unsigned* r, unsigned saddr) {
    asm volatile("ldmatrix.sync.aligned.m8n8.x4.shared.b16 {%0,%1,%2,%3}, [%4];"
        : "=r"(r[0]), "=r"(r[1]), "=r"(r[2]), "=r"(r[3]) : "r"(saddr));
}
__device__ __forceinline__ void ldm_x4_t(unsigned* r, unsigned saddr) {
    asm volatile("ldmatrix.sync.aligned.m8n8.x4.trans.shared.b16 {%0,%1,%2,%3}, [%4];"
        : "=r"(r[0]), "=r"(r[1]), "=r"(r[2]), "=r"(r[3]) : "r"(saddr));
}
__device__ __forceinline__ void mma_f16(float* d, const unsigned* a, unsigned b0, unsigned b1) {
    asm volatile(
        "mma.sync.aligned.m16n8k16.row.col.f32.f16.f16.f32 "
        "{%0,%1,%2,%3}, {%4,%5,%6,%7}, {%8,%9}, {%0,%1,%2,%3};"
        : "+f"(d[0]), "+f"(d[1]), "+f"(d[2]), "+f"(d[3])
        : "r"(a[0]), "r"(a[1]), "r"(a[2]), "r"(a[3]), "r"(b0), "r"(b1));
}
__device__ __forceinline__ unsigned h2u(float a, float b) {
    __half2 h = __floats2half2_rn(a, b);
    return *reinterpret_cast<unsigned*>(&h);
}

// ---------------- prep kernels ----------------
__global__ __launch_bounds__(256) void cvt_half_kernel(
    const float* __restrict__ in, __half* __restrict__ out, int n4)
{
    int i = blockIdx.x * blockDim.x + threadIdx.x;
    if (i >= n4) return;
    float4 v = ((const float4*)in)[i];
    ((__half2*)out)[2 * i]     = __floats2half2_rn(v.x, v.y);
    ((__half2*)out)[2 * i + 1] = __floats2half2_rn(v.z, v.w);
}

// W [K][N] fp32 -> T [N][K] fp16
__global__ __launch_bounds__(256) void transpose_half_kernel(
    const float* __restrict__ W, __half* __restrict__ T, int K, int N)
{
    __shared__ float t[32][33];
    int n0 = blockIdx.x * 32, k0 = blockIdx.y * 32;
    int tx = threadIdx.x & 31, ty = threadIdx.x >> 5;
#pragma unroll
    for (int s = 0; s < 4; s++)
        t[ty + 8 * s][tx] = W[(size_t)(k0 + ty + 8 * s) * N + n0 + tx];
    __syncthreads();
#pragma unroll
    for (int s = 0; s < 4; s++)
        T[(size_t)(n0 + ty + 8 * s) * K + k0 + tx] = __float2half(t[tx][ty + 8 * s]);
}

// ---------------- fp16 GEMM, ldmatrix + cp.async 3-stage ----------------
#define HST 40
#define TILE_H (128 * HST)
#define STG_H (2 * TILE_H)
#define GEMM_SMEM (3 * STG_H * 2)    // 61440 B

template <bool OUT_HALF>
__global__ __launch_bounds__(256) void gemm_f16_kernel(
    const __half* __restrict__ A, const __half* __restrict__ Bt,
    const float* __restrict__ bias, void* __restrict__ Cout, int N, int K)
{
    extern __shared__ __half smh[];
    const unsigned sbase = smem_u32(smh);
    const int tid  = threadIdx.x;
    const int warp = tid >> 5;
    const int lane = tid & 31;
    const int grp  = lane >> 2;
    const int tig  = lane & 3;
    const int bm = blockIdx.y * 128;
    const int bn = blockIdx.x * 128;
    const int wm = (warp >> 2) * 64;
    const int wn = (warp & 3) * 32;

    const int lrow = (lane & 7) + 8 * ((lane >> 3) & 1);
    const int lseg = lane >> 4;
    const int brow = (lane & 7) + 8 * (lane >> 4);
    const int bseg = (lane >> 3) & 1;

    float acc[4][4][4];
#pragma unroll
    for (int mt = 0; mt < 4; mt++)
#pragma unroll
        for (int nt = 0; nt < 4; nt++)
#pragma unroll
            for (int f = 0; f < 4; f++) acc[mt][nt][f] = 0.0f;

    const int NC = K >> 5;

    auto load_chunk = [&](int kc, int st) {
        unsigned ab = sbase + st * (STG_H * 2);
        unsigned bb = ab + TILE_H * 2;
        const __half* gA = A  + (size_t)bm * K + kc * 32;
        const __half* gB = Bt + (size_t)bn * K + kc * 32;
#pragma unroll
        for (int it = 0; it < 2; it++) {
            int i = tid + it * 256;
            int r = i >> 2, ch = i & 3;
            cp16(ab + r * 80 + ch * 16, gA + (size_t)r * K + ch * 8);
        }
#pragma unroll
        for (int it = 0; it < 2; it++) {
            int i = tid + it * 256;
            int r = i >> 2, ch = i & 3;
            cp16(bb + r * 80 + ch * 16, gB + (size_t)r * K + ch * 8);
        }
        CP_COMMIT();
    };

    load_chunk(0, 0);
    if (NC > 1) load_chunk(1, 1);
    for (int c = 0; c < NC; c++) {
        const int st = c % 3;
        if (c + 2 < NC)      { load_chunk(c + 2, (c + 2) % 3); CP_WAIT(2); }
        else if (c + 1 < NC) { CP_WAIT(1); }
        else                 { CP_WAIT(0); }
        __syncthreads();

        const unsigned sA = sbase + st * (STG_H * 2);
        const unsigned sB = sA + TILE_H * 2;
#pragma unroll
        for (int kb = 0; kb < 32; kb += 16) {
            unsigned a[4][4], bq[2][4];
#pragma unroll
            for (int mt = 0; mt < 4; mt++)
                ldm_x4(a[mt], sA + ((wm + mt * 16 + lrow) * HST + kb + 8 * lseg) * 2);
#pragma unroll
            for (int np = 0; np < 2; np++)
                ldm_x4(bq[np], sB + ((wn + np * 16 + brow) * HST + kb + 8 * bseg) * 2);
#pragma unroll
            for (int mt = 0; mt < 4; mt++)
#pragma unroll
                for (int np = 0; np < 2; np++) {
                    mma_f16(acc[mt][2 * np],     a[mt], bq[np][0], bq[np][1]);
                    mma_f16(acc[mt][2 * np + 1], a[mt], bq[np][2], bq[np][3]);
                }
        }
        __syncthreads();
    }

#pragma unroll
    for (int mt = 0; mt < 4; mt++) {
        int r0 = bm + wm + mt * 16 + grp;
#pragma unroll
        for (int nt = 0; nt < 4; nt++) {
            int c0 = bn + wn + nt * 8 + 2 * tig;
            float b0 = bias[c0], b1 = bias[c0 + 1];
            float v00 = acc[mt][nt][0] + b0, v01 = acc[mt][nt][1] + b1;
            float v10 = acc[mt][nt][2] + b0, v11 = acc[mt][nt][3] + b1;
            if (OUT_HALF) {
                __half* C = (__half*)Cout;
                *(unsigned*)(C + (size_t)r0 * N + c0)       = h2u(v00, v01);
                *(unsigned*)(C + (size_t)(r0 + 8) * N + c0) = h2u(v10, v11);
            } else {
                float* C = (float*)Cout;
                *(float2*)(C + (size_t)r0 * N + c0)       = make_float2(v00, v01);
                *(float2*)(C + (size_t)(r0 + 8) * N + c0) = make_float2(v10, v11);
            }
        }
    }
}

// ---------------- flash attention: cp.async double-buffered K/V ----------------
// 64 queries/block, 128 threads (4 warps), 16 query rows/warp.
// smem: Q 64x72 (single) + K 2x(64x72) + V 2x(64x72) = 46080 B
#define AQST 72
#define ATILE_B (64 * AQST * 2)            // 9216 B per tile
#define ATTN_SMEM (5 * ATILE_B)            // 46080 B

__global__ __launch_bounds__(128) void gqa_attn_f16_kernel(
    const __half* __restrict__ Q, const __half* __restrict__ KV,
    __half* __restrict__ O)
{
    extern __shared__ __half sh[];
    const unsigned sb = smem_u32(sh);
    const unsigned Qb  = sb;
    const unsigned Kb0 = sb + ATILE_B;          // stages at +0 / +ATILE_B
    const unsigned Vb0 = sb + 3 * ATILE_B;

    const int h  = blockIdx.y;
    const int b  = blockIdx.z;
    const int g  = h >> 2;
    const int q0 = blockIdx.x * 64;
    const int tid  = threadIdx.x;
    const int warp = tid >> 5;
    const int lane = tid & 31;
    const int grp  = lane >> 2;
    const int tig  = lane & 3;
    const int wq0 = warp * 16;

    const int lrow = (lane & 7) + 8 * ((lane >> 3) & 1);
    const int lseg = lane >> 4;
    const int brow = (lane & 7) + 8 * (lane >> 4);
    const int bseg = (lane >> 3) & 1;

    // load Q tile (synchronous, once)
    for (int e = tid; e < 512; e += 128) {
        int r = e >> 3, s = e & 7;
        *(uint4*)(sh + r * AQST + s * 8) =
            *(const uint4*)(Q + (size_t)(b * SEQ + q0 + r) * DMODEL + h * DKH + s * 8);
    }

    // K/V tile prefetch (cp.async): 4 cp16 per thread per operand
    auto prefetch = [&](int kt, int st) {
        unsigned kb = Kb0 + st * ATILE_B;
        unsigned vb = Vb0 + st * ATILE_B;
        const __half* base = KV + (size_t)(b * SEQ + kt) * KVSTR + g * DKH;
#pragma unroll
        for (int it = 0; it < 4; it++) {
            int i = tid + it * 128;          // 0..511
            int r = i >> 3, s = i & 7;
            const __half* rowp = base + (size_t)r * KVSTR + s * 8;
            cp16(kb + (r * AQST + s * 8) * 2, rowp);          // K cols
            cp16(vb + (r * AQST + s * 8) * 2, rowp + GDK);    // V cols
        }
        CP_COMMIT();
    };

    prefetch(0, 0);
    __syncthreads();   // Q visible to all warps

    // hoist Q fragments (loop-invariant)
    unsigned qf[4][4];
#pragma unroll
    for (int ks = 0; ks < 4; ks++)
        ldm_x4(qf[ks], Qb + ((wq0 + lrow) * AQST + ks * 16 + 8 * lseg) * 2);

    float oacc[8][4];
#pragma unroll
    for (int nt = 0; nt < 8; nt++)
#pragma unroll
        for (int f = 0; f < 4; f++) oacc[nt][f] = 0.0f;
    float mA = -1e30f, mB = -1e30f, lA = 0.0f, lB = 0.0f;
    const float scale = 0.125f;

    const int NT = SEQ / 64;
    for (int t = 0; t < NT; t++) {
        const int st = t & 1;
        if (t + 1 < NT) { prefetch((t + 1) * 64, st ^ 1); CP_WAIT(1); }
        else            { CP_WAIT(0); }
        __syncthreads();

        const unsigned Ks = Kb0 + st * ATILE_B;
        const unsigned Vs = Vb0 + st * ATILE_B;

        // S = Q K^T
        float sacc[8][4];
#pragma unroll
        for (int nt = 0; nt < 8; nt++)
#pragma unroll
            for (int f = 0; f < 4; f++) sacc[nt][f] = 0.0f;

#pragma unroll
        for (int ks = 0; ks < 4; ks++) {
            int kb = ks * 16;
#pragma unroll
            for (int np = 0; np < 4; np++) {
                unsigned bq[4];
                ldm_x4(bq, Ks + ((np * 16 + brow) * AQST + kb + 8 * bseg) * 2);
                mma_f16(sacc[2 * np],     qf[ks], bq[0], bq[1]);
                mma_f16(sacc[2 * np + 1], qf[ks], bq[2], bq[3]);
            }
        }

        // online softmax
        float rmaxA = -1e30f, rmaxB = -1e30f;
#pragma unroll
        for (int nt = 0; nt < 8; nt++) {
#pragma unroll
            for (int f = 0; f < 4; f++) sacc[nt][f] *= scale;
            rmaxA = fmaxf(rmaxA, fmaxf(sacc[nt][0], sacc[nt][1]));
            rmaxB = fmaxf(rmaxB, fmaxf(sacc[nt][2], sacc[nt][3]));
        }
#pragma unroll
        for (int o = 1; o <= 2; o <<= 1) {
            rmaxA = fmaxf(rmaxA, __shfl_xor_sync(0xffffffffu, rmaxA, o));
            rmaxB = fmaxf(rmaxB, __shfl_xor_sync(0xffffffffu, rmaxB, o));
        }
        float mnA = fmaxf(mA, rmaxA), mnB = fmaxf(mB, rmaxB);

        unsigned ph[8][2];
        float lsA = 0.0f, lsB = 0.0f;
#pragma unroll
        for (int nt = 0; nt < 8; nt++) {
            float p0 = __expf(sacc[nt][0] - mnA);
            float p1 = __expf(sacc[nt][1] - mnA);
            float p2 = __expf(sacc[nt][2] - mnB);
            float p3 = __expf(sacc[nt][3] - mnB);
            lsA += p0 + p1;  lsB += p2 + p3;
            ph[nt][0] = h2u(p0, p1);
            ph[nt][1] = h2u(p2, p3);
        }
#pragma unroll
        for (int o = 1; o <= 2; o <<= 1) {
            lsA += __shfl_xor_sync(0xffffffffu, lsA, o);
            lsB += __shfl_xor_sync(0xffffffffu, lsB, o);
        }
        float alA = __expf(mA - mnA), alB = __expf(mB - mnB);
        lA = lA * alA + lsA;  lB = lB * alB + lsB;
        mA = mnA;             mB = mnB;
#pragma unroll
        for (int nt = 0; nt < 8; nt++) {
            oacc[nt][0] *= alA; oacc[nt][1] *= alA;
            oacc[nt][2] *= alB; oacc[nt][3] *= alB;
        }

        // O += P V
#pragma unroll
        for (int ks = 0; ks < 4; ks++) {
            int kb = ks * 16;
            unsigned a[4];
            a[0] = ph[2 * ks][0];
            a[1] = ph[2 * ks][1];
            a[2] = ph[2 * ks + 1][0];
            a[3] = ph[2 * ks + 1][1];
#pragma unroll
            for (int np = 0; np < 4; np++) {
                unsigned bv[4];
                ldm_x4_t(bv, Vs + ((kb + lrow) * AQST + np * 16 + 8 * lseg) * 2);
                mma_f16(oacc[2 * np],     a, bv[0], bv[1]);
                mma_f16(oacc[2 * np + 1], a, bv[2], bv[3]);
            }
        }
        __syncthreads();   // all warps done with stage st before it is refilled
    }

    // epilogue
    float invA = 1.0f / lA, invB = 1.0f / lB;
    size_t rowA = (size_t)(b * SEQ + q0 + wq0 + grp) * DMODEL + h * DKH;
    size_t rowB = rowA + (size_t)8 * DMODEL;
#pragma unroll
    for (int nt = 0; nt < 8; nt++) {
        int c = nt * 8 + 2 * tig;
        *(unsigned*)(O + rowA + c) = h2u(oacc[nt][0] * invA, oacc[nt][1] * invA);
        *(unsigned*)(O + rowB + c) = h2u(oacc[nt][2] * invB, oacc[nt][3] * invB);
    }
}

// ---------------- host ----------------
extern "C" void kernel_launch(void* const* d_in, const int* in_sizes, int n_in,
                              void* d_out, int out_size)
{
    const float* x  = (const float*)d_in[0];
    const float* Wq = (const float*)d_in[1];
    const float* bq = (const float*)d_in[2];
    const float* Wk = (const float*)d_in[3];
    const float* bk = (const float*)d_in[4];
    const float* Wv = (const float*)d_in[5];
    const float* bv = (const float*)d_in[6];
    const float* Wo = (const float*)d_in[7];
    const float* bo = (const float*)d_in[8];
    float* out = (float*)d_out;

    __half *xh, *Qh, *KVh, *Ch, *Wqt, *Wkvt, *Wot;
    float* bkv;
    cudaGetSymbolAddress((void**)&xh,   g_xh);
    cudaGetSymbolAddress((void**)&Qh,   g_Qh);
    cudaGetSymbolAddress((void**)&KVh,  g_KVh);
    cudaGetSymbolAddress((void**)&Ch,   g_Ch);
    cudaGetSymbolAddress((void**)&Wqt,  g_Wqt);
    cudaGetSymbolAddress((void**)&Wkvt, g_Wkvt);
    cudaGetSymbolAddress((void**)&Wot,  g_Wot);
    cudaGetSymbolAddress((void**)&bkv,  g_bkv);

    cudaFuncSetAttribute(gqa_attn_f16_kernel,
                         cudaFuncAttributeMaxDynamicSharedMemorySize, ATTN_SMEM);
    cudaFuncSetAttribute(gemm_f16_kernel<true>,
                         cudaFuncAttributeMaxDynamicSharedMemorySize, GEMM_SMEM);
    cudaFuncSetAttribute(gemm_f16_kernel<false>,
                         cudaFuncAttributeMaxDynamicSharedMemorySize, GEMM_SMEM);

    // prep
    cvt_half_kernel<<<(MROWS * DMODEL / 4 + 255) / 256, 256>>>(x, xh, MROWS * DMODEL / 4);
    transpose_half_kernel<<<dim3(DMODEL / 32, DMODEL / 32), 256>>>(Wq, Wqt, DMODEL, DMODEL);
    transpose_half_kernel<<<dim3(GDK / 32, DMODEL / 32), 256>>>(Wk, Wkvt, DMODEL, GDK);
    transpose_half_kernel<<<dim3(GDK / 32, DMODEL / 32), 256>>>(
        Wv, Wkvt + (size_t)GDK * DMODEL, DMODEL, GDK);
    transpose_half_kernel<<<dim3(DMODEL / 32, DMODEL / 32), 256>>>(Wo, Wot, DMODEL, DMODEL);
    cudaMemcpyAsync(bkv,       bk, GDK * sizeof(float), cudaMemcpyDeviceToDevice);
    cudaMemcpyAsync(bkv + GDK, bv, GDK * sizeof(float), cudaMemcpyDeviceToDevice);

    // projections: Q, then fused K|V (N=1024 -> full-chip grid)
    gemm_f16_kernel<true><<<dim3(DMODEL / 128, MROWS / 128), 256, GEMM_SMEM>>>(
        xh, Wqt, bq, Qh, DMODEL, DMODEL);
    gemm_f16_kernel<true><<<dim3(KVSTR / 128, MROWS / 128), 256, GEMM_SMEM>>>(
        xh, Wkvt, bkv, KVh, KVSTR, DMODEL);

    // attention
    gqa_attn_f16_kernel<<<dim3(SEQ / 64, NH, BATCH), 128, ATTN_SMEM>>>(Qh, KVh, Ch);

    // output projection -> fp32
    gemm_f16_kernel<false><<<dim3(DMODEL / 128, MROWS / 128), 256, GEMM_SMEM>>>(
        Ch, Wot, bo, out, DMODEL, DMODEL);
}

// round 10
// speedup vs baseline: 2.0703x; 1.0045x over previous
#include <cuda_runtime.h>
#include <cuda_fp16.h>

#define BATCH 2
#define SEQ   2048
#define DMODEL 2048
#define NH    32
#define NG    8
#define DKH   64
#define GDK   (NG * DKH)     // 512
#define NQKV  (DMODEL + 2 * GDK)   // 3072 fused projection width
#define MROWS (BATCH * SEQ)  // 4096

// ---------------- scratch (no cudaMalloc allowed) ----------------
__device__ __half g_xh   [MROWS * DMODEL];
__device__ __half g_QKVh [MROWS * NQKV];     // cols: 0..2047 Q | 2048..2559 K | 2560..3071 V
__device__ __half g_Ch   [MROWS * DMODEL];
__device__ __half g_Wqkvt[NQKV * DMODEL];    // [n][k]; rows: Wq^T*0.125 | Wk^T | Wv^T
__device__ __half g_Wot  [DMODEL * DMODEL];
__device__ float  g_bqkv [NQKV];

// ---------------- helpers ----------------
__device__ __forceinline__ unsigned smem_u32(const void* p) {
    unsigned a;
    asm("{ .reg .u64 t; cvta.to.shared.u64 t, %1; cvt.u32.u64 %0, t; }" : "=r"(a) : "l"(p));
    return a;
}
__device__ __forceinline__ void cp16(unsigned saddr, const void* g) {
    asm volatile("cp.async.cg.shared.global [%0], [%1], 16;" :: "r"(saddr), "l"(g));
}
#define CP_COMMIT() asm volatile("cp.async.commit_group;" ::: "memory")
#define CP_WAIT(n)  asm volatile("cp.async.wait_group %0;" :: "n"(n) : "memory")

__device__ __forceinline__ void ldm_x4(unsigned* r, unsigned saddr) {
    asm volatile("ldmatrix.sync.aligned.m8n8.x4.shared.b16 {%0,%1,%2,%3}, [%4];"
        : "=r"(r[0]), "=r"(r[1]), "=r"(r[2]), "=r"(r[3]) : "r"(saddr));
}
__device__ __forceinline__ void ldm_x4_t(unsigned* r, unsigned saddr) {
    asm volatile("ldmatrix.sync.aligned.m8n8.x4.trans.shared.b16 {%0,%1,%2,%3}, [%4];"
        : "=r"(r[0]), "=r"(r[1]), "=r"(r[2]), "=r"(r[3]) : "r"(saddr));
}
__device__ __forceinline__ void mma_f16(float* d, const unsigned* a, unsigned b0, unsigned b1) {
    asm volatile(
        "mma.sync.aligned.m16n8k16.row.col.f32.f16.f16.f32 "
        "{%0,%1,%2,%3}, {%4,%5,%6,%7}, {%8,%9}, {%0,%1,%2,%3};"
        : "+f"(d[0]), "+f"(d[1]), "+f"(d[2]), "+f"(d[3])
        : "r"(a[0]), "r"(a[1]), "r"(a[2]), "r"(a[3]), "r"(b0), "r"(b1));
}
__device__ __forceinline__ unsigned h2u(float a, float b) {
    __half2 h = __floats2half2_rn(a, b);
    return *reinterpret_cast<unsigned*>(&h);
}

// ---------------- prep kernels ----------------
__global__ __launch_bounds__(256) void cvt_half_kernel(
    const float* __restrict__ in, __half* __restrict__ out, int n4)
{
    int i = blockIdx.x * blockDim.x + threadIdx.x;
    if (i >= n4) return;
    float4 v = ((const float4*)in)[i];
    ((__half2*)out)[2 * i]     = __floats2half2_rn(v.x, v.y);
    ((__half2*)out)[2 * i + 1] = __floats2half2_rn(v.z, v.w);
}

// W [K][N] fp32 -> T [N][K] fp16 (scaled)
__global__ __launch_bounds__(256) void transpose_half_kernel(
    const float* __restrict__ W, __half* __restrict__ T, int K, int N, float scale)
{
    __shared__ float t[32][33];
    int n0 = blockIdx.x * 32, k0 = blockIdx.y * 32;
    int tx = threadIdx.x & 31, ty = threadIdx.x >> 5;
#pragma unroll
    for (int s = 0; s < 4; s++)
        t[ty + 8 * s][tx] = W[(size_t)(k0 + ty + 8 * s) * N + n0 + tx];
    __syncthreads();
#pragma unroll
    for (int s = 0; s < 4; s++)
        T[(size_t)(n0 + ty + 8 * s) * K + k0 + tx] = __float2half(t[tx][ty + 8 * s] * scale);
}

__global__ __launch_bounds__(256) void fuse_bias_kernel(
    const float* __restrict__ bq, const float* __restrict__ bk,
    const float* __restrict__ bv, float* __restrict__ bqkv)
{
    int i = blockIdx.x * blockDim.x + threadIdx.x;
    if (i < DMODEL)                bqkv[i] = bq[i] * 0.125f;
    else if (i < DMODEL + GDK)     bqkv[i] = bk[i - DMODEL];
    else if (i < NQKV)             bqkv[i] = bv[i - DMODEL - GDK];
}

// ---------------- fp16 GEMM, ldmatrix + cp.async 3-stage ----------------
#define HST 40
#define TILE_H (128 * HST)
#define STG_H (2 * TILE_H)
#define GEMM_SMEM (3 * STG_H * 2)    // 61440 B

template <bool OUT_HALF>
__global__ __launch_bounds__(256) void gemm_f16_kernel(
    const __half* __restrict__ A, const __half* __restrict__ Bt,
    const float* __restrict__ bias, void* __restrict__ Cout, int N, int K)
{
    extern __shared__ __half smh[];
    const unsigned sbase = smem_u32(smh);
    const int tid  = threadIdx.x;
    const int warp = tid >> 5;
    const int lane = tid & 31;
    const int grp  = lane >> 2;
    const int tig  = lane & 3;
    const int bm = blockIdx.y * 128;
    const int bn = blockIdx.x * 128;
    const int wm = (warp >> 2) * 64;
    const int wn = (warp & 3) * 32;

    const int lrow = (lane & 7) + 8 * ((lane >> 3) & 1);
    const int lseg = lane >> 4;
    const int brow = (lane & 7) + 8 * (lane >> 4);
    const int bseg = (lane >> 3) & 1;

    float acc[4][4][4];
#pragma unroll
    for (int mt = 0; mt < 4; mt++)
#pragma unroll
        for (int nt = 0; nt < 4; nt++)
#pragma unroll
            for (int f = 0; f < 4; f++) acc[mt][nt][f] = 0.0f;

    const int NC = K >> 5;

    auto load_chunk = [&](int kc, int st) {
        unsigned ab = sbase + st * (STG_H * 2);
        unsigned bb = ab + TILE_H * 2;
        const __half* gA = A  + (size_t)bm * K + kc * 32;
        const __half* gB = Bt + (size_t)bn * K + kc * 32;
#pragma unroll
        for (int it = 0; it < 2; it++) {
            int i = tid + it * 256;
            int r = i >> 2, ch = i & 3;
            cp16(ab + r * 80 + ch * 16, gA + (size_t)r * K + ch * 8);
        }
#pragma unroll
        for (int it = 0; it < 2; it++) {
            int i = tid + it * 256;
            int r = i >> 2, ch = i & 3;
            cp16(bb + r * 80 + ch * 16, gB + (size_t)r * K + ch * 8);
        }
        CP_COMMIT();
    };

    load_chunk(0, 0);
    if (NC > 1) load_chunk(1, 1);
    for (int c = 0; c < NC; c++) {
        const int st = c % 3;
        if (c + 2 < NC)      { load_chunk(c + 2, (c + 2) % 3); CP_WAIT(2); }
        else if (c + 1 < NC) { CP_WAIT(1); }
        else                 { CP_WAIT(0); }
        __syncthreads();

        const unsigned sA = sbase + st * (STG_H * 2);
        const unsigned sB = sA + TILE_H * 2;
#pragma unroll
        for (int kb = 0; kb < 32; kb += 16) {
            unsigned a[4][4], bq[2][4];
#pragma unroll
            for (int mt = 0; mt < 4; mt++)
                ldm_x4(a[mt], sA + ((wm + mt * 16 + lrow) * HST + kb + 8 * lseg) * 2);
#pragma unroll
            for (int np = 0; np < 2; np++)
                ldm_x4(bq[np], sB + ((wn + np * 16 + brow) * HST + kb + 8 * bseg) * 2);
#pragma unroll
            for (int mt = 0; mt < 4; mt++)
#pragma unroll
                for (int np = 0; np < 2; np++) {
                    mma_f16(acc[mt][2 * np],     a[mt], bq[np][0], bq[np][1]);
                    mma_f16(acc[mt][2 * np + 1], a[mt], bq[np][2], bq[np][3]);
                }
        }
        __syncthreads();
    }

#pragma unroll
    for (int mt = 0; mt < 4; mt++) {
        int r0 = bm + wm + mt * 16 + grp;
#pragma unroll
        for (int nt = 0; nt < 4; nt++) {
            int c0 = bn + wn + nt * 8 + 2 * tig;
            float b0 = bias[c0], b1 = bias[c0 + 1];
            float v00 = acc[mt][nt][0] + b0, v01 = acc[mt][nt][1] + b1;
            float v10 = acc[mt][nt][2] + b0, v11 = acc[mt][nt][3] + b1;
            if (OUT_HALF) {
                __half* C = (__half*)Cout;
                *(unsigned*)(C + (size_t)r0 * N + c0)       = h2u(v00, v01);
                *(unsigned*)(C + (size_t)(r0 + 8) * N + c0) = h2u(v10, v11);
            } else {
                float* C = (float*)Cout;
                *(float2*)(C + (size_t)r0 * N + c0)       = make_float2(v00, v01);
                *(float2*)(C + (size_t)(r0 + 8) * N + c0) = make_float2(v10, v11);
            }
        }
    }
}

// ---------------- flash attention: 2 heads/block, shared K/V ----------------
// 256 threads = 8 warps. Warps 0-3 -> head h0, warps 4-7 -> head h0+1 (same group).
// Each warp: 16 query rows of its head. K/V double-buffered via cp.async.
// smem: Q 2x(64x72) + K 2x(64x72) + V 2x(64x72) = 55296 B
#define AQST 72
#define ATILE_B (64 * AQST * 2)            // 9216 B per tile
#define ATTN_SMEM (6 * ATILE_B)            // 55296 B

__global__ __launch_bounds__(256) void gqa_attn_f16_kernel(
    const __half* __restrict__ QKV, __half* __restrict__ O)
{
    extern __shared__ __half sh[];
    const unsigned sb = smem_u32(sh);
    const unsigned Qb0 = sb;                    // 2 head tiles
    const unsigned Kb0 = sb + 2 * ATILE_B;      // 2 stages
    const unsigned Vb0 = sb + 4 * ATILE_B;      // 2 stages

    const int h0 = blockIdx.y * 2;              // first head of pair
    const int b  = blockIdx.z;
    const int g  = h0 >> 2;                     // same group for h0, h0+1
    const int q0 = blockIdx.x * 64;
    const int tid  = threadIdx.x;
    const int warp = tid >> 5;
    const int hh   = warp >> 2;                 // 0/1: which head
    const int lane = tid & 31;
    const int grp  = lane >> 2;
    const int tig  = lane & 3;
    const int wq0 = (warp & 3) * 16;

    const int lrow = (lane & 7) + 8 * ((lane >> 3) & 1);
    const int lseg = lane >> 4;
    const int brow = (lane & 7) + 8 * (lane >> 4);
    const int bseg = (lane >> 3) & 1;

    // load both Q head-tiles (scale already folded into projection)
    for (int e = tid; e < 1024; e += 256) {
        int th = e >> 9, idx = e & 511;
        int r = idx >> 3, s = idx & 7;
        *(uint4*)(sh + th * (64 * AQST) + r * AQST + s * 8) =
            *(const uint4*)(QKV + (size_t)(b * SEQ + q0 + r) * NQKV + (h0 + th) * DKH + s * 8);
    }

    // K/V prefetch: K at col 2048 + g*64, V at col 2560 + g*64
    auto prefetch = [&](int kt, int st) {
        unsigned kb = Kb0 + st * ATILE_B;
        unsigned vb = Vb0 + st * ATILE_B;
        const __half* base = QKV + (size_t)(b * SEQ + kt) * NQKV + DMODEL + g * DKH;
#pragma unroll
        for (int it = 0; it < 2; it++) {
            int i = tid + it * 256;          // 0..511
            int r = i >> 3, s = i & 7;
            const __half* rowp = base + (size_t)r * NQKV + s * 8;
            cp16(kb + (r * AQST + s * 8) * 2, rowp);         // K
            cp16(vb + (r * AQST + s * 8) * 2, rowp + GDK);   // V
        }
        CP_COMMIT();
    };

    prefetch(0, 0);
    __syncthreads();   // Q visible

    // hoist Q fragments
    const unsigned Qb = Qb0 + hh * ATILE_B;
    unsigned qf[4][4];
#pragma unroll
    for (int ks = 0; ks < 4; ks++)
        ldm_x4(qf[ks], Qb + ((wq0 + lrow) * AQST + ks * 16 + 8 * lseg) * 2);

    float oacc[8][4];
#pragma unroll
    for (int nt = 0; nt < 8; nt++)
#pragma unroll
        for (int f = 0; f < 4; f++) oacc[nt][f] = 0.0f;
    float mA = -1e30f, mB = -1e30f, lA = 0.0f, lB = 0.0f;

    const int NT = SEQ / 64;
    for (int t = 0; t < NT; t++) {
        const int st = t & 1;
        if (t + 1 < NT) { prefetch((t + 1) * 64, st ^ 1); CP_WAIT(1); }
        else            { CP_WAIT(0); }
        __syncthreads();

        const unsigned Ks = Kb0 + st * ATILE_B;
        const unsigned Vs = Vb0 + st * ATILE_B;

        // S = Q K^T (scale pre-folded)
        float sacc[8][4];
#pragma unroll
        for (int nt = 0; nt < 8; nt++)
#pragma unroll
            for (int f = 0; f < 4; f++) sacc[nt][f] = 0.0f;

#pragma unroll
        for (int ks = 0; ks < 4; ks++) {
            int kb = ks * 16;
#pragma unroll
            for (int np = 0; np < 4; np++) {
                unsigned bq[4];
                ldm_x4(bq, Ks + ((np * 16 + brow) * AQST + kb + 8 * bseg) * 2);
                mma_f16(sacc[2 * np],     qf[ks], bq[0], bq[1]);
                mma_f16(sacc[2 * np + 1], qf[ks], bq[2], bq[3]);
            }
        }

        // online softmax
        float rmaxA = -1e30f, rmaxB = -1e30f;
#pragma unroll
        for (int nt = 0; nt < 8; nt++) {
            rmaxA = fmaxf(rmaxA, fmaxf(sacc[nt][0], sacc[nt][1]));
            rmaxB = fmaxf(rmaxB, fmaxf(sacc[nt][2], sacc[nt][3]));
        }
#pragma unroll
        for (int o = 1; o <= 2; o <<= 1) {
            rmaxA = fmaxf(rmaxA, __shfl_xor_sync(0xffffffffu, rmaxA, o));
            rmaxB = fmaxf(rmaxB, __shfl_xor_sync(0xffffffffu, rmaxB, o));
        }
        float mnA = fmaxf(mA, rmaxA), mnB = fmaxf(mB, rmaxB);

        unsigned ph[8][2];
        float lsA = 0.0f, lsB = 0.0f;
#pragma unroll
        for (int nt = 0; nt < 8; nt++) {
            float p0 = __expf(sacc[nt][0] - mnA);
            float p1 = __expf(sacc[nt][1] - mnA);
            float p2 = __expf(sacc[nt][2] - mnB);
            float p3 = __expf(sacc[nt][3] - mnB);
            lsA += p0 + p1;  lsB += p2 + p3;
            ph[nt][0] = h2u(p0, p1);
            ph[nt][1] = h2u(p2, p3);
        }
#pragma unroll
        for (int o = 1; o <= 2; o <<= 1) {
            lsA += __shfl_xor_sync(0xffffffffu, lsA, o);
            lsB += __shfl_xor_sync(0xffffffffu, lsB, o);
        }
        float alA = __expf(mA - mnA), alB = __expf(mB - mnB);
        lA = lA * alA + lsA;  lB = lB * alB + lsB;
        mA = mnA;             mB = mnB;
#pragma unroll
        for (int nt = 0; nt < 8; nt++) {
            oacc[nt][0] *= alA; oacc[nt][1] *= alA;
            oacc[nt][2] *= alB; oacc[nt][3] *= alB;
        }

        // O += P V
#pragma unroll
        for (int ks = 0; ks < 4; ks++) {
            int kb = ks * 16;
            unsigned a[4];
            a[0] = ph[2 * ks][0];
            a[1] = ph[2 * ks][1];
            a[2] = ph[2 * ks + 1][0];
            a[3] = ph[2 * ks + 1][1];
#pragma unroll
            for (int np = 0; np < 4; np++) {
                unsigned bv[4];
                ldm_x4_t(bv, Vs + ((kb + lrow) * AQST + np * 16 + 8 * lseg) * 2);
                mma_f16(oacc[2 * np],     a, bv[0], bv[1]);
                mma_f16(oacc[2 * np + 1], a, bv[2], bv[3]);
            }
        }
        __syncthreads();
    }

    // epilogue
    float invA = 1.0f / lA, invB = 1.0f / lB;
    size_t rowA = (size_t)(b * SEQ + q0 + wq0 + grp) * DMODEL + (h0 + hh) * DKH;
    size_t rowB = rowA + (size_t)8 * DMODEL;
#pragma unroll
    for (int nt = 0; nt < 8; nt++) {
        int c = nt * 8 + 2 * tig;
        *(unsigned*)(O + rowA + c) = h2u(oacc[nt][0] * invA, oacc[nt][1] * invA);
        *(unsigned*)(O + rowB + c) = h2u(oacc[nt][2] * invB, oacc[nt][3] * invB);
    }
}

// ---------------- host ----------------
extern "C" void kernel_launch(void* const* d_in, const int* in_sizes, int n_in,
                              void* d_out, int out_size)
{
    const float* x  = (const float*)d_in[0];
    const float* Wq = (const float*)d_in[1];
    const float* bq = (const float*)d_in[2];
    const float* Wk = (const float*)d_in[3];
    const float* bk = (const float*)d_in[4];
    const float* Wv = (const float*)d_in[5];
    const float* bv = (const float*)d_in[6];
    const float* Wo = (const float*)d_in[7];
    const float* bo = (const float*)d_in[8];
    float* out = (float*)d_out;

    __half *xh, *QKVh, *Ch, *Wqkvt, *Wot;
    float* bqkv;
    cudaGetSymbolAddress((void**)&xh,    g_xh);
    cudaGetSymbolAddress((void**)&QKVh,  g_QKVh);
    cudaGetSymbolAddress((void**)&Ch,    g_Ch);
    cudaGetSymbolAddress((void**)&Wqkvt, g_Wqkvt);
    cudaGetSymbolAddress((void**)&Wot,   g_Wot);
    cudaGetSymbolAddress((void**)&bqkv,  g_bqkv);

    cudaFuncSetAttribute(gqa_attn_f16_kernel,
                         cudaFuncAttributeMaxDynamicSharedMemorySize, ATTN_SMEM);
    cudaFuncSetAttribute(gemm_f16_kernel<true>,
                         cudaFuncAttributeMaxDynamicSharedMemorySize, GEMM_SMEM);
    cudaFuncSetAttribute(gemm_f16_kernel<false>,
                         cudaFuncAttributeMaxDynamicSharedMemorySize, GEMM_SMEM);

    // prep: x -> fp16; fused transposed weights (Q scaled by 1/8); fused bias
    cvt_half_kernel<<<(MROWS * DMODEL / 4 + 255) / 256, 256>>>(x, xh, MROWS * DMODEL / 4);
    transpose_half_kernel<<<dim3(DMODEL / 32, DMODEL / 32), 256>>>(
        Wq, Wqkvt, DMODEL, DMODEL, 0.125f);
    transpose_half_kernel<<<dim3(GDK / 32, DMODEL / 32), 256>>>(
        Wk, Wqkvt + (size_t)DMODEL * DMODEL, DMODEL, GDK, 1.0f);
    transpose_half_kernel<<<dim3(GDK / 32, DMODEL / 32), 256>>>(
        Wv, Wqkvt + (size_t)(DMODEL + GDK) * DMODEL, DMODEL, GDK, 1.0f);
    transpose_half_kernel<<<dim3(DMODEL / 32, DMODEL / 32), 256>>>(
        Wo, Wot, DMODEL, DMODEL, 1.0f);
    fuse_bias_kernel<<<(NQKV + 255) / 256, 256>>>(bq, bk, bv, bqkv);

    // fused QKV projection (N=3072)
    gemm_f16_kernel<true><<<dim3(NQKV / 128, MROWS / 128), 256, GEMM_SMEM>>>(
        xh, Wqkvt, bqkv, QKVh, NQKV, DMODEL);

    // attention: 2 heads per block
    gqa_attn_f16_kernel<<<dim3(SEQ / 64, NH / 2, BATCH), 256, ATTN_SMEM>>>(QKVh, Ch);

    // output projection -> fp32
    gemm_f16_kernel<false><<<dim3(DMODEL / 128, MROWS / 128), 256, GEMM_SMEM>>>(
        Ch, Wot, bo, out, DMODEL, DMODEL);
}